// round 1
// baseline (speedup 1.0000x reference)
#include <cuda_runtime.h>
#include <math.h>

#define BSZ   32
#define LQ    512
#define DM    768
#define NHID  192
#define KC    5
#define DI    1536
#define DS    16
#define DTR   48
#define DCONV 4
#define ML    (BSZ*LQ)        // 16384 rows
#define EPSV  1e-5f

// ---------------- scratch buffers (global __device__ arrays; no allocs) ----
__device__ float g_h  [ML*NHID];          // 12.6 MB
__device__ float g_h2 [ML*NHID];          // 12.6 MB
__device__ float g_x1 [ML*DM];            // 50 MB
__device__ float g_xn [ML*DM];            // 50 MB
__device__ float g_xz [(size_t)ML*2*DI];  // 201 MB  (xm | z)
__device__ float g_xmc[ML*DI];            // 100 MB
__device__ float g_dbc[ML*(DTR+2*DS)];    // 5.2 MB
__device__ float g_del[ML*DI];            // 100 MB
__device__ float g_y  [ML*DI];            // 100 MB
__device__ float g_mo [ML*DM];            // 50 MB
__device__ float g_gt [ML*DM];            // 50 MB
__device__ float g_xf [ML*DM];            // 50 MB
__device__ float g_rm [ML];
__device__ float g_rs [ML];
__device__ float g_cm [4096];
__device__ float g_cs [4096];

// ---------------- generic SGEMM: C = act(A[M,K] * W[N,K]^T + bias) ---------
// act: 0 none, 2 softplus, 3 sigmoid
__global__ void sgemm(const float* __restrict__ A, int lda,
                      const float* __restrict__ W, int ldw,
                      const float* __restrict__ bias,
                      float* __restrict__ C, int ldc,
                      int M, int N, int Kd, int act)
{
    __shared__ float As[64][17];   // [row][k]  (pad -> conflict-free writes)
    __shared__ float Ws[16][65];   // [k][col]

    const int tx = threadIdx.x, ty = threadIdx.y;
    const int tid = ty * 16 + tx;
    const int row0 = blockIdx.y * 64, col0 = blockIdx.x * 64;

    float acc[4][4];
#pragma unroll
    for (int i = 0; i < 4; i++)
#pragma unroll
        for (int j = 0; j < 4; j++) acc[i][j] = 0.f;

    for (int kt = 0; kt < Kd; kt += 16) {
#pragma unroll
        for (int i = 0; i < 4; i++) {
            int e = i * 256 + tid;
            int r = e >> 4, k = e & 15;
            int gr = row0 + r, gk = kt + k;
            As[r][k] = (gr < M && gk < Kd) ? A[(long)gr * lda + gk] : 0.f;
        }
#pragma unroll
        for (int i = 0; i < 4; i++) {
            int e = i * 256 + tid;
            int n = e >> 4, k = e & 15;
            int gn = col0 + n, gk = kt + k;
            Ws[k][n] = (gn < N && gk < Kd) ? W[(long)gn * ldw + gk] : 0.f;
        }
        __syncthreads();
#pragma unroll
        for (int k = 0; k < 16; k++) {
            float a[4], w[4];
#pragma unroll
            for (int i = 0; i < 4; i++) a[i] = As[ty * 4 + i][k];
#pragma unroll
            for (int j = 0; j < 4; j++) w[j] = Ws[k][tx * 4 + j];
#pragma unroll
            for (int i = 0; i < 4; i++)
#pragma unroll
                for (int j = 0; j < 4; j++)
                    acc[i][j] = fmaf(a[i], w[j], acc[i][j]);
        }
        __syncthreads();
    }

#pragma unroll
    for (int i = 0; i < 4; i++) {
        int r = row0 + ty * 4 + i;
        if (r >= M) continue;
#pragma unroll
        for (int j = 0; j < 4; j++) {
            int c = col0 + tx * 4 + j;
            if (c >= N) continue;
            float v = acc[i][j];
            if (bias) v += bias[c];
            if (act == 2) v = (v > 20.f) ? v : log1pf(expf(v));      // softplus
            else if (act == 3) v = 1.f / (1.f + expf(-v));           // sigmoid
            C[(long)r * ldc + c] = v;
        }
    }
}

// ---------------- BatchNorm stats over rows (axes 0,1) --------------------
__global__ void bn_stats(const float* __restrict__ src, int M, int N,
                         float* __restrict__ mean, float* __restrict__ rstd)
{
    int c = blockIdx.x * 32 + threadIdx.x;
    if (c >= N) return;
    float s = 0.f, sq = 0.f;
    for (int r = threadIdx.y; r < M; r += blockDim.y) {
        float v = src[(long)r * N + c];
        s += v; sq += v * v;
    }
    __shared__ float sh[32][33], sh2[32][33];
    sh[threadIdx.y][threadIdx.x] = s;
    sh2[threadIdx.y][threadIdx.x] = sq;
    __syncthreads();
    if (threadIdx.y == 0) {
        for (int i = 1; i < 32; i++) { s += sh[i][threadIdx.x]; sq += sh2[i][threadIdx.x]; }
        float m = s / (float)M;
        mean[c] = m;
        rstd[c] = rsqrtf(fmaxf(sq / (float)M - m * m, 0.f) + EPSV);
    }
}

// ---------------- BN apply (+optional silu, +optional residual) -----------
__global__ void bn_apply(const float* __restrict__ src, const float* __restrict__ resid,
                         float* __restrict__ dst,
                         const float* __restrict__ mean, const float* __restrict__ rstd,
                         const float* __restrict__ g, const float* __restrict__ b,
                         long total, int N, int dosilu)
{
    long i = (long)blockIdx.x * blockDim.x + threadIdx.x;
    if (i >= total) return;
    int c = (int)(i % N);
    float v = (src[i] - mean[c]) * rstd[c] * g[c] + b[c];
    if (dosilu) v = v / (1.f + expf(-v));
    if (resid) v += resid[i];
    dst[i] = v;
}

// ---------------- depthwise conv K=5, same padding ------------------------
__global__ void dwconv5(const float* __restrict__ src, const float* __restrict__ w,
                        float* __restrict__ dst)
{
    long i = (long)blockIdx.x * blockDim.x + threadIdx.x;
    if (i >= (long)ML * NHID) return;
    int c = (int)(i % NHID);
    long bl = i / NHID;
    int l = (int)(bl % LQ);
    long b = bl / LQ;
    float acc = 0.f;
#pragma unroll
    for (int k = 0; k < KC; k++) {
        int ll = l + k - 2;
        if (ll >= 0 && ll < LQ)
            acc += src[(b * LQ + ll) * NHID + c] * w[c * KC + k];
    }
    dst[i] = acc;
}

// ---------------- causal depthwise conv K=4 + bias + silu -----------------
// reads xm = g_xz[:, :DI] (row stride 2*DI), writes g_xmc (row stride DI)
__global__ void cconv4(const float* __restrict__ xz, const float* __restrict__ w,
                       const float* __restrict__ cb, float* __restrict__ dst)
{
    long i = (long)blockIdx.x * blockDim.x + threadIdx.x;
    if (i >= (long)ML * DI) return;
    int c = (int)(i % DI);
    long bl = i / DI;
    int l = (int)(bl % LQ);
    long b = bl / LQ;
    float acc = cb[c];
#pragma unroll
    for (int k = 0; k < DCONV; k++) {
        int ll = l + k - (DCONV - 1);
        if (ll >= 0)
            acc += xz[(b * LQ + ll) * (2 * DI) + c] * w[c * DCONV + k];
    }
    dst[i] = acc / (1.f + expf(-acc));   // silu
}

// ---------------- LayerNorm row stats -------------------------------------
__global__ void ln_stats(const float* __restrict__ x, float* __restrict__ rm,
                         float* __restrict__ rs, int N)
{
    int r = blockIdx.x;
    const float* row = x + (long)r * N;
    float s = 0.f, sq = 0.f;
    for (int c = threadIdx.x; c < N; c += blockDim.x) {
        float v = row[c]; s += v; sq += v * v;
    }
    __shared__ float sh[256], sh2[256];
    sh[threadIdx.x] = s; sh2[threadIdx.x] = sq;
    __syncthreads();
    for (int st = 128; st > 0; st >>= 1) {
        if (threadIdx.x < st) { sh[threadIdx.x] += sh[threadIdx.x + st]; sh2[threadIdx.x] += sh2[threadIdx.x + st]; }
        __syncthreads();
    }
    if (threadIdx.x == 0) {
        float m = sh[0] / (float)N;
        rm[r] = m;
        rs[r] = rsqrtf(fmaxf(sh2[0] / (float)N - m * m, 0.f) + EPSV);
    }
}

// ---------------- LN apply elementwise ------------------------------------
__global__ void ln_apply(const float* __restrict__ x, const float* __restrict__ rm,
                         const float* __restrict__ rs, const float* __restrict__ g,
                         const float* __restrict__ b, float* __restrict__ dst,
                         long total, int N)
{
    long i = (long)blockIdx.x * blockDim.x + threadIdx.x;
    if (i >= total) return;
    int c = (int)(i % N);
    long r = i / N;
    dst[i] = (x[i] - rm[r]) * rs[r] * g[c] + b[c];
}

// ---------------- feat_attr: max over L of LN(x1) -------------------------
__global__ void feat_attr_k(const float* __restrict__ x1, const float* __restrict__ rm,
                            const float* __restrict__ rs, const float* __restrict__ g,
                            const float* __restrict__ b, float* __restrict__ out)
{
    int d = blockIdx.x * blockDim.x + threadIdx.x;
    int bb = blockIdx.y;
    if (d >= DM) return;
    float gd = g[d], bd = b[d];
    float best = -1e30f;
    for (int l = 0; l < LQ; l++) {
        long row = (long)bb * LQ + l;
        float v = (x1[row * DM + d] - rm[row]) * rs[row] * gd + bd;
        best = fmaxf(best, v);
    }
    out[(long)bb * DM + d] = best;
}

// ---------------- feat_id: mean over L of LN(x_final) ---------------------
__global__ void feat_id_k(const float* __restrict__ xf, const float* __restrict__ rm,
                          const float* __restrict__ rs, const float* __restrict__ g,
                          const float* __restrict__ b, float* __restrict__ out)
{
    int d = blockIdx.x * blockDim.x + threadIdx.x;
    int bb = blockIdx.y;
    if (d >= DM) return;
    float acc = 0.f;
    for (int l = 0; l < LQ; l++) {
        long row = (long)bb * LQ + l;
        acc += (xf[row * DM + d] - rm[row]) * rs[row];
    }
    out[(long)bb * DM + d] = (acc / (float)LQ) * g[d] + b[d];
}

// ---------------- feat_id_bn: BN over batch axis (two-pass) ---------------
__global__ void idbn_k(const float* __restrict__ fid, const float* __restrict__ g,
                       const float* __restrict__ b, float* __restrict__ out)
{
    int d = blockIdx.x * blockDim.x + threadIdx.x;
    if (d >= DM) return;
    float s = 0.f;
    for (int bb = 0; bb < BSZ; bb++) s += fid[(long)bb * DM + d];
    float m = s / (float)BSZ;
    float vq = 0.f;
    for (int bb = 0; bb < BSZ; bb++) { float dv = fid[(long)bb * DM + d] - m; vq += dv * dv; }
    float rst = rsqrtf(vq / (float)BSZ + EPSV);
    for (int bb = 0; bb < BSZ; bb++)
        out[(long)bb * DM + d] = (fid[(long)bb * DM + d] - m) * rst * g[d] + b[d];
}

// ---------------- selective scan ------------------------------------------
// y[b,l,d] = (scan(h; exp(delta*A), delta*B*u) . C  + u*D) * silu(z)
// fast path: A[d,s] == -(s+1)  ->  exp(delta*A_s) = p^(s+1), p = exp(-delta)
__global__ void scan_k(const float* __restrict__ xmc, const float* __restrict__ del,
                       const float* __restrict__ dbc, const float* __restrict__ xz,
                       const float* __restrict__ A_log, const float* __restrict__ Dp,
                       float* __restrict__ y)
{
    int b = blockIdx.y;
    int d = blockIdx.x * 128 + threadIdx.x;
    float A[DS], h[DS];
    bool fast = true;
#pragma unroll
    for (int s = 0; s < DS; s++) {
        A[s] = -expf(A_log[(long)d * DS + s]);
        h[s] = 0.f;
        fast = fast && (fabsf(A[s] + (float)(s + 1)) < 1e-4f * (float)(s + 1));
    }
    float Dpv = Dp[d];
    __shared__ float sBC[2 * DS];

    for (int l = 0; l < LQ; l++) {
        long rb = (long)b * LQ + l;
        if (threadIdx.x < 2 * DS)
            sBC[threadIdx.x] = dbc[rb * (DTR + 2 * DS) + DTR + threadIdx.x];
        __syncthreads();
        float dv = del[rb * DI + d];
        float uv = xmc[rb * DI + d];
        float zv = xz[rb * 2 * DI + DI + d];
        float du = dv * uv;
        float yv = 0.f;
        if (fast) {
            float p = expf(-dv), e = 1.f;
#pragma unroll
            for (int s = 0; s < DS; s++) {
                e *= p;
                h[s] = h[s] * e + du * sBC[s];
                yv += h[s] * sBC[DS + s];
            }
        } else {
#pragma unroll
            for (int s = 0; s < DS; s++) {
                float e = expf(dv * A[s]);
                h[s] = h[s] * e + du * sBC[s];
                yv += h[s] * sBC[DS + s];
            }
        }
        yv += uv * Dpv;
        float sz = zv / (1.f + expf(-zv));
        y[rb * DI + d] = yv * sz;
        __syncthreads();
    }
}

// ---------------- x_final = x1 + mamba_out*gate + x -----------------------
__global__ void xfinal_k(const float* __restrict__ x1, const float* __restrict__ mo,
                         const float* __restrict__ gt, const float* __restrict__ x,
                         float* __restrict__ xf, long total)
{
    long i = (long)blockIdx.x * blockDim.x + threadIdx.x;
    if (i >= total) return;
    xf[i] = x1[i] + mo[i] * gt[i] + x[i];
}

// ======================== host launcher ====================================
static inline dim3 gemm_grid(int M, int N) { return dim3((N + 63) / 64, (M + 63) / 64); }

extern "C" void kernel_launch(void* const* d_in, const int* in_sizes, int n_in,
                              void* d_out, int out_size)
{
    (void)in_sizes; (void)n_in; (void)out_size;
    const float* x         = (const float*)d_in[0];
    const float* sq_w      = (const float*)d_in[1];
    const float* sq_bn_g   = (const float*)d_in[2];
    const float* sq_bn_b   = (const float*)d_in[3];
    const float* dw_w      = (const float*)d_in[4];
    const float* dw_bn_g   = (const float*)d_in[5];
    const float* dw_bn_b   = (const float*)d_in[6];
    const float* ex_w      = (const float*)d_in[7];
    const float* ex_bn_g   = (const float*)d_in[8];
    const float* ex_bn_b   = (const float*)d_in[9];
    const float* attr_g    = (const float*)d_in[10];
    const float* attr_b    = (const float*)d_in[11];
    const float* mnorm_g   = (const float*)d_in[12];
    const float* mnorm_b   = (const float*)d_in[13];
    const float* in_proj_w = (const float*)d_in[14];
    const float* conv_w    = (const float*)d_in[15];
    const float* conv_b    = (const float*)d_in[16];
    const float* xproj_w   = (const float*)d_in[17];
    const float* dtproj_w  = (const float*)d_in[18];
    const float* dtproj_b  = (const float*)d_in[19];
    const float* A_log     = (const float*)d_in[20];
    const float* D_param   = (const float*)d_in[21];
    const float* out_proj_w= (const float*)d_in[22];
    const float* gate_w    = (const float*)d_in[23];
    const float* gate_b    = (const float*)d_in[24];
    const float* idn_g     = (const float*)d_in[25];
    const float* idn_b     = (const float*)d_in[26];
    const float* idbn_g    = (const float*)d_in[27];
    const float* idbn_b    = (const float*)d_in[28];
    float* out = (float*)d_out;

    float *h, *h2, *x1, *xn, *xz, *xmc, *dbc, *del, *y, *mo, *gt, *xf, *rm, *rs, *cm, *cs;
    cudaGetSymbolAddress((void**)&h,   g_h);
    cudaGetSymbolAddress((void**)&h2,  g_h2);
    cudaGetSymbolAddress((void**)&x1,  g_x1);
    cudaGetSymbolAddress((void**)&xn,  g_xn);
    cudaGetSymbolAddress((void**)&xz,  g_xz);
    cudaGetSymbolAddress((void**)&xmc, g_xmc);
    cudaGetSymbolAddress((void**)&dbc, g_dbc);
    cudaGetSymbolAddress((void**)&del, g_del);
    cudaGetSymbolAddress((void**)&y,   g_y);
    cudaGetSymbolAddress((void**)&mo,  g_mo);
    cudaGetSymbolAddress((void**)&gt,  g_gt);
    cudaGetSymbolAddress((void**)&xf,  g_xf);
    cudaGetSymbolAddress((void**)&rm,  g_rm);
    cudaGetSymbolAddress((void**)&rs,  g_rs);
    cudaGetSymbolAddress((void**)&cm,  g_cm);
    cudaGetSymbolAddress((void**)&cs,  g_cs);

    dim3 tb(16, 16);
    const long tD  = (long)ML * DM;
    const long tH  = (long)ML * NHID;
    const long tI  = (long)ML * DI;

    // 1. squeeze proj + BN + silu
    sgemm<<<gemm_grid(ML, NHID), tb>>>(x, DM, sq_w, DM, nullptr, h, NHID, ML, NHID, DM, 0);
    bn_stats<<<NHID / 32, dim3(32, 32)>>>(h, ML, NHID, cm, cs);
    bn_apply<<<(tH + 255) / 256, 256>>>(h, nullptr, h, cm, cs, sq_bn_g, sq_bn_b, tH, NHID, 1);

    // 2. depthwise conv5 + BN + silu
    dwconv5<<<(tH + 255) / 256, 256>>>(h, dw_w, h2);
    bn_stats<<<NHID / 32, dim3(32, 32)>>>(h2, ML, NHID, cm, cs);
    bn_apply<<<(tH + 255) / 256, 256>>>(h2, nullptr, h2, cm, cs, dw_bn_g, dw_bn_b, tH, NHID, 1);

    // 3. expand proj + BN, residual add -> x1
    sgemm<<<gemm_grid(ML, DM), tb>>>(h2, NHID, ex_w, NHID, nullptr, mo, DM, ML, DM, NHID, 0);
    bn_stats<<<DM / 32, dim3(32, 32)>>>(mo, ML, DM, cm, cs);
    bn_apply<<<(tD + 255) / 256, 256>>>(mo, x, x1, cm, cs, ex_bn_g, ex_bn_b, tD, DM, 0);

    // 4/5. LN stats on x1; feat_attr; xn
    ln_stats<<<ML, 256>>>(x1, rm, rs, DM);
    feat_attr_k<<<dim3(DM / 256, BSZ), 256>>>(x1, rm, rs, attr_g, attr_b, out);
    ln_apply<<<(tD + 255) / 256, 256>>>(x1, rm, rs, mnorm_g, mnorm_b, xn, tD, DM);

    // 6. in_proj -> xz (xm | z)
    sgemm<<<gemm_grid(ML, 2 * DI), tb>>>(xn, DM, in_proj_w, DM, nullptr, xz, 2 * DI, ML, 2 * DI, DM, 0);

    // 7. causal conv4 + bias + silu -> xmc
    cconv4<<<(tI + 255) / 256, 256>>>(xz, conv_w, conv_b, xmc);

    // 8. xproj -> dbc (dt | B | C)
    sgemm<<<gemm_grid(ML, DTR + 2 * DS), tb>>>(xmc, DI, xproj_w, DI, nullptr, dbc, DTR + 2 * DS, ML, DTR + 2 * DS, DI, 0);

    // 9. dtproj + bias + softplus -> delta
    sgemm<<<gemm_grid(ML, DI), tb>>>(dbc, DTR + 2 * DS, dtproj_w, DTR, dtproj_b, del, DI, ML, DI, DTR, 2);

    // 10/11. selective scan (+ *silu(z)) -> y
    scan_k<<<dim3(DI / 128, BSZ), 128>>>(xmc, del, dbc, xz, A_log, D_param, y);

    // 12. out_proj -> mamba_out
    sgemm<<<gemm_grid(ML, DM), tb>>>(y, DI, out_proj_w, DI, nullptr, mo, DM, ML, DM, DI, 0);

    // 13. gate = sigmoid(xn @ gate_w^T + gate_b)
    sgemm<<<gemm_grid(ML, DM), tb>>>(xn, DM, gate_w, DM, gate_b, gt, DM, ML, DM, DM, 3);

    // 14. x_final = x1 + mo*gate + x
    xfinal_k<<<(tD + 255) / 256, 256>>>(x1, mo, gt, x, xf, tD);

    // 15. LN(x_final) -> feat_id (mean over L)
    ln_stats<<<ML, 256>>>(xf, rm, rs, DM);
    feat_id_k<<<dim3(DM / 256, BSZ), 256>>>(xf, rm, rs, idn_g, idn_b, out + (long)BSZ * DM);

    // 16. BN over batch -> feat_id_bn
    idbn_k<<<DM / 256, 256>>>(out + (long)BSZ * DM, idbn_g, idbn_b, out + 2L * BSZ * DM);
}

// round 3
// speedup vs baseline: 2.6240x; 2.6240x over previous
#include <cuda_runtime.h>
#include <cuda_bf16.h>
#include <math.h>
#include <stdint.h>

#define BSZ   32
#define LQ    512
#define DM    768
#define NHID  192
#define KC    5
#define DI    1536
#define DS    16
#define DTR   48
#define DCONV 4
#define ML    (BSZ*LQ)        // 16384 rows
#define EPSV  1e-5f

// mma-GEMM tiling: CTA 128x128, K-chunk 32, 8 warps (4x2), warp tile 32x64
#define TGK      32
#define APITCH   36                         // floats per smem row (pad: conflict-free)
#define ABUF     (128*APITCH)               // floats per A (or B) buffer
#define TG_SMEMF (4*ABUF)                   // 2 bufs x (A+B) = 18432 floats
#define TG_SMEMB (TG_SMEMF*4)               // 73728 bytes

// ---------------- scratch buffers (global __device__ arrays; no allocs) ----
__device__ float g_h  [ML*NHID];
__device__ float g_h2 [ML*NHID];
__device__ float g_x1 [ML*DM];
__device__ float g_xn [ML*DM];
__device__ float g_xz [(size_t)ML*2*DI];
__device__ float g_xmc[ML*DI];
__device__ float g_dbc[ML*(DTR+2*DS)];
__device__ float g_del[ML*DI];
__device__ float g_y  [ML*DI];
__device__ float g_mo [ML*DM];
__device__ float g_gt [ML*DM];
__device__ float g_xf [ML*DM];
__device__ float g_rm [ML];
__device__ float g_rs [ML];
__device__ float g_cm [4096];
__device__ float g_cs [4096];

// ===================== helpers =============================================
__device__ __forceinline__ uint32_t f2tf(float v) {
    uint32_t u;
    asm("cvt.rna.tf32.f32 %0, %1;" : "=r"(u) : "f"(v));
    return u;
}
__device__ __forceinline__ void mma_tf32(float* d, const uint32_t* a, const uint32_t* b) {
    asm volatile(
        "mma.sync.aligned.m16n8k8.row.col.f32.tf32.tf32.f32 "
        "{%0,%1,%2,%3}, {%4,%5,%6,%7}, {%8,%9}, {%0,%1,%2,%3};"
        : "+f"(d[0]), "+f"(d[1]), "+f"(d[2]), "+f"(d[3])
        : "r"(a[0]), "r"(a[1]), "r"(a[2]), "r"(a[3]), "r"(b[0]), "r"(b[1]));
}

// ===================== tf32 tensor GEMM ====================================
// C[M,N] = act(A[M,K] * W[N,K]^T + bias);  act: 0 none, 2 softplus, 3 sigmoid
// M multiple of 128; K multiple of 4.
__global__ void __launch_bounds__(256, 1)
tgemm(const float* __restrict__ A, int lda,
      const float* __restrict__ W, int ldw,
      const float* __restrict__ bias,
      float* __restrict__ C, int ldc,
      int M, int N, int K, int act)
{
    extern __shared__ float smem[];
    const int tid = threadIdx.x;
    const int wid = tid >> 5, lane = tid & 31;
    const int g = lane >> 2, t = lane & 3;          // groupID / threadID_in_group
    const int wm = wid & 3, wn = wid >> 2;          // warp position in 4x2 grid
    const int row0 = blockIdx.y * 128, col0 = blockIdx.x * 128;

    const int lr = tid >> 3;       // 0..31 -> but we reuse per-i below
    const int lq = tid & 7;
    (void)lr; (void)lq;

    float acc[2][8][4];
#pragma unroll
    for (int mt = 0; mt < 2; mt++)
#pragma unroll
        for (int nt = 0; nt < 8; nt++)
#pragma unroll
            for (int j = 0; j < 4; j++) acc[mt][nt][j] = 0.f;

    const int nch = (K + TGK - 1) / TGK;

    float4 pa[4], pb[4];

    // ---- load chunk into regs (guarded) ----
    auto ldg_chunk = [&](int ch) {
        const int k0 = ch * TGK;
#pragma unroll
        for (int i = 0; i < 4; i++) {
            int e = i * 256 + tid;
            int r = e >> 3, q = e & 7;
            int gk = k0 + q * 4;
            pa[i] = (gk < K) ? *(const float4*)(A + (long)(row0 + r) * lda + gk)
                             : make_float4(0.f, 0.f, 0.f, 0.f);
            int n = col0 + r;
            pb[i] = (gk < K && n < N) ? *(const float4*)(W + (long)n * ldw + gk)
                                      : make_float4(0.f, 0.f, 0.f, 0.f);
        }
    };
    // ---- store regs to smem buffer (tf32-converted) ----
    auto sts_chunk = [&](int buf) {
        uint32_t* As = (uint32_t*)(smem + buf * 2 * ABUF);
        uint32_t* Bs = As + ABUF;
#pragma unroll
        for (int i = 0; i < 4; i++) {
            int e = i * 256 + tid;
            int r = e >> 3, q = e & 7;
            int o = r * APITCH + q * 4;
            As[o + 0] = f2tf(pa[i].x); As[o + 1] = f2tf(pa[i].y);
            As[o + 2] = f2tf(pa[i].z); As[o + 3] = f2tf(pa[i].w);
            Bs[o + 0] = f2tf(pb[i].x); Bs[o + 1] = f2tf(pb[i].y);
            Bs[o + 2] = f2tf(pb[i].z); Bs[o + 3] = f2tf(pb[i].w);
        }
    };
    // ---- compute one chunk from smem buffer ----
    auto compute_chunk = [&](int buf) {
        const uint32_t* As = (const uint32_t*)(smem + buf * 2 * ABUF);
        const uint32_t* Bs = As + ABUF;
#pragma unroll
        for (int ks = 0; ks < 4; ks++) {
            const int k = ks * 8;
            uint32_t af[2][4], bf[8][2];
#pragma unroll
            for (int mt = 0; mt < 2; mt++) {
                int ar = wm * 32 + mt * 16;
                af[mt][0] = As[(ar + g)     * APITCH + k + t];
                af[mt][1] = As[(ar + g + 8) * APITCH + k + t];
                af[mt][2] = As[(ar + g)     * APITCH + k + t + 4];
                af[mt][3] = As[(ar + g + 8) * APITCH + k + t + 4];
            }
#pragma unroll
            for (int nt = 0; nt < 8; nt++) {
                int br = wn * 64 + nt * 8;
                bf[nt][0] = Bs[(br + g) * APITCH + k + t];
                bf[nt][1] = Bs[(br + g) * APITCH + k + t + 4];
            }
#pragma unroll
            for (int mt = 0; mt < 2; mt++)
#pragma unroll
                for (int nt = 0; nt < 8; nt++)
                    mma_tf32(acc[mt][nt], af[mt], bf[nt]);
        }
    };

    ldg_chunk(0);
    sts_chunk(0);
    __syncthreads();
    for (int ch = 1; ch < nch; ch++) {
        ldg_chunk(ch);
        compute_chunk((ch - 1) & 1);
        sts_chunk(ch & 1);
        __syncthreads();
    }
    compute_chunk((nch - 1) & 1);

    // ---- epilogue ----
#pragma unroll
    for (int mt = 0; mt < 2; mt++) {
        int r0 = row0 + wm * 32 + mt * 16 + g;
#pragma unroll
        for (int nt = 0; nt < 8; nt++) {
            int c0 = col0 + wn * 64 + nt * 8 + t * 2;
            if (c0 >= N) continue;
#pragma unroll
            for (int half = 0; half < 2; half++) {
                int r = r0 + half * 8;
                float v0 = acc[mt][nt][half * 2 + 0];
                float v1 = acc[mt][nt][half * 2 + 1];
                if (bias) { v0 += bias[c0]; v1 += bias[c0 + 1]; }
                if (act == 2) {
                    v0 = (v0 > 20.f) ? v0 : log1pf(expf(v0));
                    v1 = (v1 > 20.f) ? v1 : log1pf(expf(v1));
                } else if (act == 3) {
                    v0 = 1.f / (1.f + expf(-v0));
                    v1 = 1.f / (1.f + expf(-v1));
                }
                *(float2*)(C + (long)r * ldc + c0) = make_float2(v0, v1);
            }
        }
    }
}

// ===================== non-GEMM kernels ====================================
__global__ void bn_stats(const float* __restrict__ src, int M, int N,
                         float* __restrict__ mean, float* __restrict__ rstd)
{
    int c = blockIdx.x * 32 + threadIdx.x;
    if (c >= N) return;
    float s = 0.f, sq = 0.f;
    for (int r = threadIdx.y; r < M; r += blockDim.y) {
        float v = src[(long)r * N + c];
        s += v; sq += v * v;
    }
    __shared__ float sh[32][33], sh2[32][33];
    sh[threadIdx.y][threadIdx.x] = s;
    sh2[threadIdx.y][threadIdx.x] = sq;
    __syncthreads();
    if (threadIdx.y == 0) {
        for (int i = 1; i < 32; i++) { s += sh[i][threadIdx.x]; sq += sh2[i][threadIdx.x]; }
        float m = s / (float)M;
        mean[c] = m;
        rstd[c] = rsqrtf(fmaxf(sq / (float)M - m * m, 0.f) + EPSV);
    }
}

__global__ void bn_apply(const float* __restrict__ src, const float* __restrict__ resid,
                         float* __restrict__ dst,
                         const float* __restrict__ mean, const float* __restrict__ rstd,
                         const float* __restrict__ g, const float* __restrict__ b,
                         long total, int N, int dosilu)
{
    long i = (long)blockIdx.x * blockDim.x + threadIdx.x;
    if (i >= total) return;
    int c = (int)(i % N);
    float v = (src[i] - mean[c]) * rstd[c] * g[c] + b[c];
    if (dosilu) v = v / (1.f + expf(-v));
    if (resid) v += resid[i];
    dst[i] = v;
}

__global__ void dwconv5(const float* __restrict__ src, const float* __restrict__ w,
                        float* __restrict__ dst)
{
    long i = (long)blockIdx.x * blockDim.x + threadIdx.x;
    if (i >= (long)ML * NHID) return;
    int c = (int)(i % NHID);
    long bl = i / NHID;
    int l = (int)(bl % LQ);
    long b = bl / LQ;
    float acc = 0.f;
#pragma unroll
    for (int k = 0; k < KC; k++) {
        int ll = l + k - 2;
        if (ll >= 0 && ll < LQ)
            acc += src[(b * LQ + ll) * NHID + c] * w[c * KC + k];
    }
    dst[i] = acc;
}

__global__ void cconv4(const float* __restrict__ xz, const float* __restrict__ w,
                       const float* __restrict__ cb, float* __restrict__ dst)
{
    long i = (long)blockIdx.x * blockDim.x + threadIdx.x;
    if (i >= (long)ML * DI) return;
    int c = (int)(i % DI);
    long bl = i / DI;
    int l = (int)(bl % LQ);
    long b = bl / LQ;
    float acc = cb[c];
#pragma unroll
    for (int k = 0; k < DCONV; k++) {
        int ll = l + k - (DCONV - 1);
        if (ll >= 0)
            acc += xz[(b * LQ + ll) * (2 * DI) + c] * w[c * DCONV + k];
    }
    dst[i] = acc / (1.f + expf(-acc));
}

__global__ void ln_stats(const float* __restrict__ x, float* __restrict__ rm,
                         float* __restrict__ rs, int N)
{
    int r = blockIdx.x;
    const float* row = x + (long)r * N;
    float s = 0.f, sq = 0.f;
    for (int c = threadIdx.x; c < N; c += blockDim.x) {
        float v = row[c]; s += v; sq += v * v;
    }
    __shared__ float sh[256], sh2[256];
    sh[threadIdx.x] = s; sh2[threadIdx.x] = sq;
    __syncthreads();
    for (int st = 128; st > 0; st >>= 1) {
        if (threadIdx.x < st) { sh[threadIdx.x] += sh[threadIdx.x + st]; sh2[threadIdx.x] += sh2[threadIdx.x + st]; }
        __syncthreads();
    }
    if (threadIdx.x == 0) {
        float m = sh[0] / (float)N;
        rm[r] = m;
        rs[r] = rsqrtf(fmaxf(sh2[0] / (float)N - m * m, 0.f) + EPSV);
    }
}

__global__ void ln_apply(const float* __restrict__ x, const float* __restrict__ rm,
                         const float* __restrict__ rs, const float* __restrict__ g,
                         const float* __restrict__ b, float* __restrict__ dst,
                         long total, int N)
{
    long i = (long)blockIdx.x * blockDim.x + threadIdx.x;
    if (i >= total) return;
    int c = (int)(i % N);
    long r = i / N;
    dst[i] = (x[i] - rm[r]) * rs[r] * g[c] + b[c];
}

__global__ void feat_attr_k(const float* __restrict__ x1, const float* __restrict__ rm,
                            const float* __restrict__ rs, const float* __restrict__ g,
                            const float* __restrict__ b, float* __restrict__ out)
{
    int d = blockIdx.x * blockDim.x + threadIdx.x;
    int bb = blockIdx.y;
    if (d >= DM) return;
    float gd = g[d], bd = b[d];
    float best = -1e30f;
    for (int l = 0; l < LQ; l++) {
        long row = (long)bb * LQ + l;
        float v = (x1[row * DM + d] - rm[row]) * rs[row] * gd + bd;
        best = fmaxf(best, v);
    }
    out[(long)bb * DM + d] = best;
}

__global__ void feat_id_k(const float* __restrict__ xf, const float* __restrict__ rm,
                          const float* __restrict__ rs, const float* __restrict__ g,
                          const float* __restrict__ b, float* __restrict__ out)
{
    int d = blockIdx.x * blockDim.x + threadIdx.x;
    int bb = blockIdx.y;
    if (d >= DM) return;
    float acc = 0.f;
    for (int l = 0; l < LQ; l++) {
        long row = (long)bb * LQ + l;
        acc += (xf[row * DM + d] - rm[row]) * rs[row];
    }
    out[(long)bb * DM + d] = (acc / (float)LQ) * g[d] + b[d];
}

__global__ void idbn_k(const float* __restrict__ fid, const float* __restrict__ g,
                       const float* __restrict__ b, float* __restrict__ out)
{
    int d = blockIdx.x * blockDim.x + threadIdx.x;
    if (d >= DM) return;
    float s = 0.f;
    for (int bb = 0; bb < BSZ; bb++) s += fid[(long)bb * DM + d];
    float m = s / (float)BSZ;
    float vq = 0.f;
    for (int bb = 0; bb < BSZ; bb++) { float dv = fid[(long)bb * DM + d] - m; vq += dv * dv; }
    float rst = rsqrtf(vq / (float)BSZ + EPSV);
    for (int bb = 0; bb < BSZ; bb++)
        out[(long)bb * DM + d] = (fid[(long)bb * DM + d] - m) * rst * g[d] + b[d];
}

__global__ void scan_k(const float* __restrict__ xmc, const float* __restrict__ del,
                       const float* __restrict__ dbc, const float* __restrict__ xz,
                       const float* __restrict__ A_log, const float* __restrict__ Dp,
                       float* __restrict__ y)
{
    int b = blockIdx.y;
    int d = blockIdx.x * 128 + threadIdx.x;
    float A[DS], h[DS];
    bool fast = true;
#pragma unroll
    for (int s = 0; s < DS; s++) {
        A[s] = -expf(A_log[(long)d * DS + s]);
        h[s] = 0.f;
        fast = fast && (fabsf(A[s] + (float)(s + 1)) < 1e-4f * (float)(s + 1));
    }
    float Dpv = Dp[d];
    __shared__ float sBC[2 * DS];

    for (int l = 0; l < LQ; l++) {
        long rb = (long)b * LQ + l;
        if (threadIdx.x < 2 * DS)
            sBC[threadIdx.x] = dbc[rb * (DTR + 2 * DS) + DTR + threadIdx.x];
        __syncthreads();
        float dv = del[rb * DI + d];
        float uv = xmc[rb * DI + d];
        float zv = xz[rb * 2 * DI + DI + d];
        float du = dv * uv;
        float yv = 0.f;
        if (fast) {
            float p = expf(-dv), e = 1.f;
#pragma unroll
            for (int s = 0; s < DS; s++) {
                e *= p;
                h[s] = h[s] * e + du * sBC[s];
                yv += h[s] * sBC[DS + s];
            }
        } else {
#pragma unroll
            for (int s = 0; s < DS; s++) {
                float e = expf(dv * A[s]);
                h[s] = h[s] * e + du * sBC[s];
                yv += h[s] * sBC[DS + s];
            }
        }
        yv += uv * Dpv;
        float sz = zv / (1.f + expf(-zv));
        y[rb * DI + d] = yv * sz;
        __syncthreads();
    }
}

__global__ void xfinal_k(const float* __restrict__ x1, const float* __restrict__ mo,
                         const float* __restrict__ gt, const float* __restrict__ x,
                         float* __restrict__ xf, long total)
{
    long i = (long)blockIdx.x * blockDim.x + threadIdx.x;
    if (i >= total) return;
    xf[i] = x1[i] + mo[i] * gt[i] + x[i];
}

// ======================== host launcher ====================================
static inline dim3 tg_grid(int N) { return dim3((N + 127) / 128, ML / 128); }

extern "C" void kernel_launch(void* const* d_in, const int* in_sizes, int n_in,
                              void* d_out, int out_size)
{
    (void)in_sizes; (void)n_in; (void)out_size;
    const float* x         = (const float*)d_in[0];
    const float* sq_w      = (const float*)d_in[1];
    const float* sq_bn_g   = (const float*)d_in[2];
    const float* sq_bn_b   = (const float*)d_in[3];
    const float* dw_w      = (const float*)d_in[4];
    const float* dw_bn_g   = (const float*)d_in[5];
    const float* dw_bn_b   = (const float*)d_in[6];
    const float* ex_w      = (const float*)d_in[7];
    const float* ex_bn_g   = (const float*)d_in[8];
    const float* ex_bn_b   = (const float*)d_in[9];
    const float* attr_g    = (const float*)d_in[10];
    const float* attr_b    = (const float*)d_in[11];
    const float* mnorm_g   = (const float*)d_in[12];
    const float* mnorm_b   = (const float*)d_in[13];
    const float* in_proj_w = (const float*)d_in[14];
    const float* conv_w    = (const float*)d_in[15];
    const float* conv_b    = (const float*)d_in[16];
    const float* xproj_w   = (const float*)d_in[17];
    const float* dtproj_w  = (const float*)d_in[18];
    const float* dtproj_b  = (const float*)d_in[19];
    const float* A_log     = (const float*)d_in[20];
    const float* D_param   = (const float*)d_in[21];
    const float* out_proj_w= (const float*)d_in[22];
    const float* gate_w    = (const float*)d_in[23];
    const float* gate_b    = (const float*)d_in[24];
    const float* idn_g     = (const float*)d_in[25];
    const float* idn_b     = (const float*)d_in[26];
    const float* idbn_g    = (const float*)d_in[27];
    const float* idbn_b    = (const float*)d_in[28];
    float* out = (float*)d_out;

    float *h, *h2, *x1, *xn, *xz, *xmc, *dbc, *del, *y, *mo, *gt, *xf, *rm, *rs, *cm, *cs;
    cudaGetSymbolAddress((void**)&h,   g_h);
    cudaGetSymbolAddress((void**)&h2,  g_h2);
    cudaGetSymbolAddress((void**)&x1,  g_x1);
    cudaGetSymbolAddress((void**)&xn,  g_xn);
    cudaGetSymbolAddress((void**)&xz,  g_xz);
    cudaGetSymbolAddress((void**)&xmc, g_xmc);
    cudaGetSymbolAddress((void**)&dbc, g_dbc);
    cudaGetSymbolAddress((void**)&del, g_del);
    cudaGetSymbolAddress((void**)&y,   g_y);
    cudaGetSymbolAddress((void**)&mo,  g_mo);
    cudaGetSymbolAddress((void**)&gt,  g_gt);
    cudaGetSymbolAddress((void**)&xf,  g_xf);
    cudaGetSymbolAddress((void**)&rm,  g_rm);
    cudaGetSymbolAddress((void**)&rs,  g_rs);
    cudaGetSymbolAddress((void**)&cm,  g_cm);
    cudaGetSymbolAddress((void**)&cs,  g_cs);

    cudaFuncSetAttribute(tgemm, cudaFuncAttributeMaxDynamicSharedMemorySize, TG_SMEMB);

    const long tD  = (long)ML * DM;
    const long tH  = (long)ML * NHID;
    const long tI  = (long)ML * DI;

    // 1. squeeze proj + BN + silu
    tgemm<<<tg_grid(NHID), 256, TG_SMEMB>>>(x, DM, sq_w, DM, nullptr, h, NHID, ML, NHID, DM, 0);
    bn_stats<<<NHID / 32, dim3(32, 32)>>>(h, ML, NHID, cm, cs);
    bn_apply<<<(tH + 255) / 256, 256>>>(h, nullptr, h, cm, cs, sq_bn_g, sq_bn_b, tH, NHID, 1);

    // 2. depthwise conv5 + BN + silu
    dwconv5<<<(tH + 255) / 256, 256>>>(h, dw_w, h2);
    bn_stats<<<NHID / 32, dim3(32, 32)>>>(h2, ML, NHID, cm, cs);
    bn_apply<<<(tH + 255) / 256, 256>>>(h2, nullptr, h2, cm, cs, dw_bn_g, dw_bn_b, tH, NHID, 1);

    // 3. expand proj + BN, residual add -> x1
    tgemm<<<tg_grid(DM), 256, TG_SMEMB>>>(h2, NHID, ex_w, NHID, nullptr, mo, DM, ML, DM, NHID, 0);
    bn_stats<<<DM / 32, dim3(32, 32)>>>(mo, ML, DM, cm, cs);
    bn_apply<<<(tD + 255) / 256, 256>>>(mo, x, x1, cm, cs, ex_bn_g, ex_bn_b, tD, DM, 0);

    // 4/5. LN stats on x1; feat_attr; xn
    ln_stats<<<ML, 256>>>(x1, rm, rs, DM);
    feat_attr_k<<<dim3(DM / 256, BSZ), 256>>>(x1, rm, rs, attr_g, attr_b, out);
    ln_apply<<<(tD + 255) / 256, 256>>>(x1, rm, rs, mnorm_g, mnorm_b, xn, tD, DM);

    // 6. in_proj -> xz (xm | z)
    tgemm<<<tg_grid(2 * DI), 256, TG_SMEMB>>>(xn, DM, in_proj_w, DM, nullptr, xz, 2 * DI, ML, 2 * DI, DM, 0);

    // 7. causal conv4 + bias + silu -> xmc
    cconv4<<<(tI + 255) / 256, 256>>>(xz, conv_w, conv_b, xmc);

    // 8. xproj -> dbc (dt | B | C)
    tgemm<<<tg_grid(DTR + 2 * DS), 256, TG_SMEMB>>>(xmc, DI, xproj_w, DI, nullptr, dbc, DTR + 2 * DS, ML, DTR + 2 * DS, DI, 0);

    // 9. dtproj + bias + softplus -> delta
    tgemm<<<tg_grid(DI), 256, TG_SMEMB>>>(dbc, DTR + 2 * DS, dtproj_w, DTR, dtproj_b, del, DI, ML, DI, DTR, 2);

    // 10/11. selective scan (+ *silu(z)) -> y
    scan_k<<<dim3(DI / 128, BSZ), 128>>>(xmc, del, dbc, xz, A_log, D_param, y);

    // 12. out_proj -> mamba_out
    tgemm<<<tg_grid(DM), 256, TG_SMEMB>>>(y, DI, out_proj_w, DI, nullptr, mo, DM, ML, DM, DI, 0);

    // 13. gate = sigmoid(xn @ gate_w^T + gate_b)
    tgemm<<<tg_grid(DM), 256, TG_SMEMB>>>(xn, DM, gate_w, DM, gate_b, gt, DM, ML, DM, DM, 3);

    // 14. x_final = x1 + mo*gate + x
    xfinal_k<<<(tD + 255) / 256, 256>>>(x1, mo, gt, x, xf, tD);

    // 15. LN(x_final) -> feat_id (mean over L)
    ln_stats<<<ML, 256>>>(xf, rm, rs, DM);
    feat_id_k<<<dim3(DM / 256, BSZ), 256>>>(xf, rm, rs, idn_g, idn_b, out + (long)BSZ * DM);

    // 16. BN over batch -> feat_id_bn
    idbn_k<<<DM / 256, 256>>>(out + (long)BSZ * DM, idbn_g, idbn_b, out + 2L * BSZ * DM);
}

// round 4
// speedup vs baseline: 3.4673x; 1.3214x over previous
#include <cuda_runtime.h>
#include <cuda_fp16.h>
#include <math.h>
#include <stdint.h>

#define BSZ   32
#define LQ    512
#define DM    768
#define NHID  192
#define KC    5
#define DI    1536
#define DS    16
#define DTR   48
#define DCONV 4
#define ML    (BSZ*LQ)        // 16384 rows
#define EPSV  1e-5f

// fp16-mma GEMM tiling: CTA 128x128, K-chunk 32 (2 ksteps of 16), 8 warps 4x2
#define TGK     32
#define PITCHW  20                      // 4B-words per smem row (16 data + 4 pad)
#define TILEW   (128*PITCHW)            // words per tile buffer (10KB)
#define TG_SMEMB (4*TILEW*4)            // 2 bufs x (A+B) = 40960 bytes

// ---------------- scratch buffers (global __device__ arrays; no allocs) ----
__device__ float g_h  [ML*NHID];
__device__ float g_h2 [ML*NHID];
__device__ float g_x1 [ML*DM];
__device__ float g_xn [ML*DM];
__device__ float g_xz [(size_t)ML*2*DI];
__device__ float g_xmc[ML*DI];
__device__ float g_dbc[ML*(DTR+2*DS)];
__device__ float g_del[ML*DI];
__device__ float g_y  [ML*DI];
__device__ float g_mo [ML*DM];
__device__ float g_gt [ML*DM];
__device__ float g_xf [ML*DM];
__device__ float g_rm [ML];
__device__ float g_rs [ML];
__device__ float g_cm [4096];
__device__ float g_cs [4096];

// ===================== helpers =============================================
__device__ __forceinline__ uint32_t pack_h2(float a, float b) {
    __half2 h = __floats2half2_rn(a, b);
    return *(uint32_t*)&h;
}
__device__ __forceinline__ void mma_f16(float* d, const uint32_t* a, const uint32_t* b) {
    asm volatile(
        "mma.sync.aligned.m16n8k16.row.col.f32.f16.f16.f32 "
        "{%0,%1,%2,%3}, {%4,%5,%6,%7}, {%8,%9}, {%0,%1,%2,%3};"
        : "+f"(d[0]), "+f"(d[1]), "+f"(d[2]), "+f"(d[3])
        : "r"(a[0]), "r"(a[1]), "r"(a[2]), "r"(a[3]), "r"(b[0]), "r"(b[1]));
}

// ===================== fp16 tensor GEMM ====================================
// C[M,N] = act(A[M,K] * W[N,K]^T + bias);  act: 0 none, 2 softplus, 3 sigmoid
// M multiple of 128; K,N multiples of 4 (N even).
__global__ void __launch_bounds__(256, 2)
tgemm(const float* __restrict__ A, int lda,
      const float* __restrict__ W, int ldw,
      const float* __restrict__ bias,
      float* __restrict__ C, int ldc,
      int M, int N, int K, int act)
{
    extern __shared__ uint32_t smem[];    // half2 words
    const int tid = threadIdx.x;
    const int wid = tid >> 5, lane = tid & 31;
    const int g = lane >> 2, t = lane & 3;
    const int wm = wid & 3, wn = wid >> 2;
    const int row0 = blockIdx.y * 128, col0 = blockIdx.x * 128;

    float acc[2][8][4];
#pragma unroll
    for (int mt = 0; mt < 2; mt++)
#pragma unroll
        for (int nt = 0; nt < 8; nt++)
#pragma unroll
            for (int j = 0; j < 4; j++) acc[mt][nt][j] = 0.f;

    const int nch = (K + TGK - 1) / TGK;

    uint32_t pa[4][2], pb[4][2];

    auto ldg_chunk = [&](int ch) {
        const int k0 = ch * TGK;
#pragma unroll
        for (int i = 0; i < 4; i++) {
            int e = i * 256 + tid;
            int r = e >> 3, q = e & 7;
            int gk = k0 + q * 4;
            float4 va = (gk < K) ? *(const float4*)(A + (long)(row0 + r) * lda + gk)
                                 : make_float4(0.f, 0.f, 0.f, 0.f);
            int n = col0 + r;
            float4 vb = (gk < K && n < N) ? *(const float4*)(W + (long)n * ldw + gk)
                                          : make_float4(0.f, 0.f, 0.f, 0.f);
            pa[i][0] = pack_h2(va.x, va.y); pa[i][1] = pack_h2(va.z, va.w);
            pb[i][0] = pack_h2(vb.x, vb.y); pb[i][1] = pack_h2(vb.z, vb.w);
        }
    };
    auto sts_chunk = [&](int buf) {
        uint32_t* As = smem + buf * 2 * TILEW;
        uint32_t* Bs = As + TILEW;
#pragma unroll
        for (int i = 0; i < 4; i++) {
            int e = i * 256 + tid;
            int r = e >> 3, q = e & 7;
            int o = r * PITCHW + q * 2;
            As[o] = pa[i][0]; As[o + 1] = pa[i][1];
            Bs[o] = pb[i][0]; Bs[o + 1] = pb[i][1];
        }
    };
    auto compute_chunk = [&](int buf) {
        const uint32_t* As = smem + buf * 2 * TILEW;
        const uint32_t* Bs = As + TILEW;
#pragma unroll
        for (int ks = 0; ks < 2; ks++) {
            const int kw = ks * 8;
            uint32_t af[2][4], bf[8][2];
#pragma unroll
            for (int mt = 0; mt < 2; mt++) {
                int ar = wm * 32 + mt * 16;
                af[mt][0] = As[(ar + g)     * PITCHW + kw + t];
                af[mt][1] = As[(ar + g + 8) * PITCHW + kw + t];
                af[mt][2] = As[(ar + g)     * PITCHW + kw + t + 4];
                af[mt][3] = As[(ar + g + 8) * PITCHW + kw + t + 4];
            }
#pragma unroll
            for (int nt = 0; nt < 8; nt++) {
                int br = wn * 64 + nt * 8;
                bf[nt][0] = Bs[(br + g) * PITCHW + kw + t];
                bf[nt][1] = Bs[(br + g) * PITCHW + kw + t + 4];
            }
#pragma unroll
            for (int mt = 0; mt < 2; mt++)
#pragma unroll
                for (int nt = 0; nt < 8; nt++)
                    mma_f16(acc[mt][nt], af[mt], bf[nt]);
        }
    };

    ldg_chunk(0);
    sts_chunk(0);
    __syncthreads();
    for (int ch = 1; ch < nch; ch++) {
        ldg_chunk(ch);
        compute_chunk((ch - 1) & 1);
        sts_chunk(ch & 1);
        __syncthreads();
    }
    compute_chunk((nch - 1) & 1);

    // ---- epilogue ----
#pragma unroll
    for (int mt = 0; mt < 2; mt++) {
        int r0 = row0 + wm * 32 + mt * 16 + g;
#pragma unroll
        for (int nt = 0; nt < 8; nt++) {
            int c0 = col0 + wn * 64 + nt * 8 + t * 2;
            if (c0 >= N) continue;
#pragma unroll
            for (int half = 0; half < 2; half++) {
                int r = r0 + half * 8;
                float v0 = acc[mt][nt][half * 2 + 0];
                float v1 = acc[mt][nt][half * 2 + 1];
                if (bias) { v0 += bias[c0]; v1 += bias[c0 + 1]; }
                if (act == 2) {
                    v0 = (v0 > 20.f) ? v0 : log1pf(expf(v0));
                    v1 = (v1 > 20.f) ? v1 : log1pf(expf(v1));
                } else if (act == 3) {
                    v0 = 1.f / (1.f + expf(-v0));
                    v1 = 1.f / (1.f + expf(-v1));
                }
                *(float2*)(C + (long)r * ldc + c0) = make_float2(v0, v1);
            }
        }
    }
}

// ===================== non-GEMM kernels ====================================
__global__ void bn_stats(const float* __restrict__ src, int M, int N,
                         float* __restrict__ mean, float* __restrict__ rstd)
{
    int c = blockIdx.x * 32 + threadIdx.x;
    if (c >= N) return;
    float s = 0.f, sq = 0.f;
    for (int r = threadIdx.y; r < M; r += blockDim.y) {
        float v = src[(long)r * N + c];
        s += v; sq += v * v;
    }
    __shared__ float sh[32][33], sh2[32][33];
    sh[threadIdx.y][threadIdx.x] = s;
    sh2[threadIdx.y][threadIdx.x] = sq;
    __syncthreads();
    if (threadIdx.y == 0) {
        for (int i = 1; i < 32; i++) { s += sh[i][threadIdx.x]; sq += sh2[i][threadIdx.x]; }
        float m = s / (float)M;
        mean[c] = m;
        rstd[c] = rsqrtf(fmaxf(sq / (float)M - m * m, 0.f) + EPSV);
    }
}

__global__ void bn_apply(const float* __restrict__ src, const float* __restrict__ resid,
                         float* __restrict__ dst,
                         const float* __restrict__ mean, const float* __restrict__ rstd,
                         const float* __restrict__ g, const float* __restrict__ b,
                         long total, int N, int dosilu)
{
    long i = (long)blockIdx.x * blockDim.x + threadIdx.x;
    if (i >= total) return;
    int c = (int)(i % N);
    float v = (src[i] - mean[c]) * rstd[c] * g[c] + b[c];
    if (dosilu) v = v / (1.f + expf(-v));
    if (resid) v += resid[i];
    dst[i] = v;
}

__global__ void dwconv5(const float* __restrict__ src, const float* __restrict__ w,
                        float* __restrict__ dst)
{
    long i = (long)blockIdx.x * blockDim.x + threadIdx.x;
    if (i >= (long)ML * NHID) return;
    int c = (int)(i % NHID);
    long bl = i / NHID;
    int l = (int)(bl % LQ);
    long b = bl / LQ;
    float acc = 0.f;
#pragma unroll
    for (int k = 0; k < KC; k++) {
        int ll = l + k - 2;
        if (ll >= 0 && ll < LQ)
            acc += src[(b * LQ + ll) * NHID + c] * w[c * KC + k];
    }
    dst[i] = acc;
}

__global__ void cconv4(const float* __restrict__ xz, const float* __restrict__ w,
                       const float* __restrict__ cb, float* __restrict__ dst)
{
    long i = (long)blockIdx.x * blockDim.x + threadIdx.x;
    if (i >= (long)ML * DI) return;
    int c = (int)(i % DI);
    long bl = i / DI;
    int l = (int)(bl % LQ);
    long b = bl / LQ;
    float acc = cb[c];
#pragma unroll
    for (int k = 0; k < DCONV; k++) {
        int ll = l + k - (DCONV - 1);
        if (ll >= 0)
            acc += xz[(b * LQ + ll) * (2 * DI) + c] * w[c * DCONV + k];
    }
    dst[i] = acc / (1.f + expf(-acc));
}

// ---------------- fused LN: stats + apply + save stats --------------------
__global__ void ln_fuse(const float* __restrict__ x, const float* __restrict__ g,
                        const float* __restrict__ b, float* __restrict__ dst,
                        float* __restrict__ rm, float* __restrict__ rs)
{
    int r = blockIdx.x;
    const float* row = x + (long)r * DM;
    float v[3];
#pragma unroll
    for (int i = 0; i < 3; i++) v[i] = row[threadIdx.x + i * 256];
    float s = v[0] + v[1] + v[2];
    float sq = v[0] * v[0] + v[1] * v[1] + v[2] * v[2];
    __shared__ float sh[256], sh2[256];
    sh[threadIdx.x] = s; sh2[threadIdx.x] = sq;
    __syncthreads();
    for (int st = 128; st > 0; st >>= 1) {
        if (threadIdx.x < st) { sh[threadIdx.x] += sh[threadIdx.x + st]; sh2[threadIdx.x] += sh2[threadIdx.x + st]; }
        __syncthreads();
    }
    float m = sh[0] / (float)DM;
    float rstd = rsqrtf(fmaxf(sh2[0] / (float)DM - m * m, 0.f) + EPSV);
    if (threadIdx.x == 0) { rm[r] = m; rs[r] = rstd; }
    float* drow = dst + (long)r * DM;
#pragma unroll
    for (int i = 0; i < 3; i++) {
        int c = threadIdx.x + i * 256;
        drow[c] = (v[i] - m) * rstd * g[c] + b[c];
    }
}

// ---------------- fused x_final + LN stats ---------------------------------
__global__ void xfinal_ln(const float* __restrict__ x1, const float* __restrict__ mo,
                          const float* __restrict__ gt, const float* __restrict__ x,
                          float* __restrict__ xf, float* __restrict__ rm,
                          float* __restrict__ rs)
{
    int r = blockIdx.x;
    long base = (long)r * DM;
    float v[3];
#pragma unroll
    for (int i = 0; i < 3; i++) {
        int c = threadIdx.x + i * 256;
        v[i] = x1[base + c] + mo[base + c] * gt[base + c] + x[base + c];
        xf[base + c] = v[i];
    }
    float s = v[0] + v[1] + v[2];
    float sq = v[0] * v[0] + v[1] * v[1] + v[2] * v[2];
    __shared__ float sh[256], sh2[256];
    sh[threadIdx.x] = s; sh2[threadIdx.x] = sq;
    __syncthreads();
    for (int st = 128; st > 0; st >>= 1) {
        if (threadIdx.x < st) { sh[threadIdx.x] += sh[threadIdx.x + st]; sh2[threadIdx.x] += sh2[threadIdx.x + st]; }
        __syncthreads();
    }
    if (threadIdx.x == 0) {
        float m = sh[0] / (float)DM;
        rm[r] = m;
        rs[r] = rsqrtf(fmaxf(sh2[0] / (float)DM - m * m, 0.f) + EPSV);
    }
}

__global__ void feat_attr_k(const float* __restrict__ x1, const float* __restrict__ rm,
                            const float* __restrict__ rs, const float* __restrict__ g,
                            const float* __restrict__ b, float* __restrict__ out)
{
    int d = blockIdx.x * blockDim.x + threadIdx.x;
    int bb = blockIdx.y;
    if (d >= DM) return;
    float gd = g[d], bd = b[d];
    float best = -1e30f;
    for (int l = 0; l < LQ; l++) {
        long row = (long)bb * LQ + l;
        float v = (x1[row * DM + d] - rm[row]) * rs[row] * gd + bd;
        best = fmaxf(best, v);
    }
    out[(long)bb * DM + d] = best;
}

__global__ void feat_id_k(const float* __restrict__ xf, const float* __restrict__ rm,
                          const float* __restrict__ rs, const float* __restrict__ g,
                          const float* __restrict__ b, float* __restrict__ out)
{
    int d = blockIdx.x * blockDim.x + threadIdx.x;
    int bb = blockIdx.y;
    if (d >= DM) return;
    float acc = 0.f;
    for (int l = 0; l < LQ; l++) {
        long row = (long)bb * LQ + l;
        acc += (xf[row * DM + d] - rm[row]) * rs[row];
    }
    out[(long)bb * DM + d] = (acc / (float)LQ) * g[d] + b[d];
}

__global__ void idbn_k(const float* __restrict__ fid, const float* __restrict__ g,
                       const float* __restrict__ b, float* __restrict__ out)
{
    int d = blockIdx.x * blockDim.x + threadIdx.x;
    if (d >= DM) return;
    float s = 0.f;
    for (int bb = 0; bb < BSZ; bb++) s += fid[(long)bb * DM + d];
    float m = s / (float)BSZ;
    float vq = 0.f;
    for (int bb = 0; bb < BSZ; bb++) { float dv = fid[(long)bb * DM + d] - m; vq += dv * dv; }
    float rst = rsqrtf(vq / (float)BSZ + EPSV);
    for (int bb = 0; bb < BSZ; bb++)
        out[(long)bb * DM + d] = (fid[(long)bb * DM + d] - m) * rst * g[d] + b[d];
}

// ---------------- selective scan (barrier-free, prefetched) ----------------
__global__ void __launch_bounds__(128)
scan_k(const float* __restrict__ xmc, const float* __restrict__ del,
       const float* __restrict__ dbc, const float* __restrict__ xz,
       const float* __restrict__ A_log, const float* __restrict__ Dp,
       float* __restrict__ y)
{
    int b = blockIdx.y;
    int d = blockIdx.x * 128 + threadIdx.x;
    float A[DS], h[DS];
    bool fast = true;
#pragma unroll
    for (int s = 0; s < DS; s++) {
        A[s] = -expf(A_log[(long)d * DS + s]);
        h[s] = 0.f;
        fast = fast && (fabsf(A[s] + (float)(s + 1)) < 1e-4f * (float)(s + 1));
    }
    float Dpv = Dp[d];
    const long rb0 = (long)b * LQ;
    const float* dbcb = dbc + rb0 * (DTR + 2 * DS) + DTR;

    // current-row values
    float dv = del[rb0 * DI + d];
    float uv = xmc[rb0 * DI + d];
    float zv = xz[rb0 * 2 * DI + DI + d];
    float4 bc[8];
#pragma unroll
    for (int i = 0; i < 8; i++) bc[i] = *(const float4*)(dbcb + i * 4);

    for (int l = 0; l < LQ; l++) {
        // prefetch next row
        float dvn = 0.f, uvn = 0.f, zvn = 0.f;
        float4 bcn[8];
#pragma unroll
        for (int i = 0; i < 8; i++) bcn[i] = make_float4(0.f, 0.f, 0.f, 0.f);
        if (l + 1 < LQ) {
            long rb = rb0 + l + 1;
            dvn = del[rb * DI + d];
            uvn = xmc[rb * DI + d];
            zvn = xz[rb * 2 * DI + DI + d];
            const float* p = dbcb + (long)(l + 1) * (DTR + 2 * DS);
#pragma unroll
            for (int i = 0; i < 8; i++) bcn[i] = *(const float4*)(p + i * 4);
        }

        float Bv[DS], Cv[DS];
#pragma unroll
        for (int i = 0; i < 4; i++) {
            Bv[i * 4 + 0] = bc[i].x; Bv[i * 4 + 1] = bc[i].y;
            Bv[i * 4 + 2] = bc[i].z; Bv[i * 4 + 3] = bc[i].w;
            Cv[i * 4 + 0] = bc[i + 4].x; Cv[i * 4 + 1] = bc[i + 4].y;
            Cv[i * 4 + 2] = bc[i + 4].z; Cv[i * 4 + 3] = bc[i + 4].w;
        }

        float du = dv * uv;
        float yv = 0.f;
        if (fast) {
            float p = expf(-dv), e = 1.f;
#pragma unroll
            for (int s = 0; s < DS; s++) {
                e *= p;
                h[s] = h[s] * e + du * Bv[s];
                yv += h[s] * Cv[s];
            }
        } else {
#pragma unroll
            for (int s = 0; s < DS; s++) {
                float e = expf(dv * A[s]);
                h[s] = h[s] * e + du * Bv[s];
                yv += h[s] * Cv[s];
            }
        }
        yv += uv * Dpv;
        float sz = zv / (1.f + expf(-zv));
        y[(rb0 + l) * DI + d] = yv * sz;

        dv = dvn; uv = uvn; zv = zvn;
#pragma unroll
        for (int i = 0; i < 8; i++) bc[i] = bcn[i];
    }
}

// ======================== host launcher ====================================
static inline dim3 tg_grid(int N) { return dim3((N + 127) / 128, ML / 128); }

extern "C" void kernel_launch(void* const* d_in, const int* in_sizes, int n_in,
                              void* d_out, int out_size)
{
    (void)in_sizes; (void)n_in; (void)out_size;
    const float* x         = (const float*)d_in[0];
    const float* sq_w      = (const float*)d_in[1];
    const float* sq_bn_g   = (const float*)d_in[2];
    const float* sq_bn_b   = (const float*)d_in[3];
    const float* dw_w      = (const float*)d_in[4];
    const float* dw_bn_g   = (const float*)d_in[5];
    const float* dw_bn_b   = (const float*)d_in[6];
    const float* ex_w      = (const float*)d_in[7];
    const float* ex_bn_g   = (const float*)d_in[8];
    const float* ex_bn_b   = (const float*)d_in[9];
    const float* attr_g    = (const float*)d_in[10];
    const float* attr_b    = (const float*)d_in[11];
    const float* mnorm_g   = (const float*)d_in[12];
    const float* mnorm_b   = (const float*)d_in[13];
    const float* in_proj_w = (const float*)d_in[14];
    const float* conv_w    = (const float*)d_in[15];
    const float* conv_b    = (const float*)d_in[16];
    const float* xproj_w   = (const float*)d_in[17];
    const float* dtproj_w  = (const float*)d_in[18];
    const float* dtproj_b  = (const float*)d_in[19];
    const float* A_log     = (const float*)d_in[20];
    const float* D_param   = (const float*)d_in[21];
    const float* out_proj_w= (const float*)d_in[22];
    const float* gate_w    = (const float*)d_in[23];
    const float* gate_b    = (const float*)d_in[24];
    const float* idn_g     = (const float*)d_in[25];
    const float* idn_b     = (const float*)d_in[26];
    const float* idbn_g    = (const float*)d_in[27];
    const float* idbn_b    = (const float*)d_in[28];
    float* out = (float*)d_out;

    float *h, *h2, *x1, *xn, *xz, *xmc, *dbc, *del, *y, *mo, *gt, *xf, *rm, *rs, *cm, *cs;
    cudaGetSymbolAddress((void**)&h,   g_h);
    cudaGetSymbolAddress((void**)&h2,  g_h2);
    cudaGetSymbolAddress((void**)&x1,  g_x1);
    cudaGetSymbolAddress((void**)&xn,  g_xn);
    cudaGetSymbolAddress((void**)&xz,  g_xz);
    cudaGetSymbolAddress((void**)&xmc, g_xmc);
    cudaGetSymbolAddress((void**)&dbc, g_dbc);
    cudaGetSymbolAddress((void**)&del, g_del);
    cudaGetSymbolAddress((void**)&y,   g_y);
    cudaGetSymbolAddress((void**)&mo,  g_mo);
    cudaGetSymbolAddress((void**)&gt,  g_gt);
    cudaGetSymbolAddress((void**)&xf,  g_xf);
    cudaGetSymbolAddress((void**)&rm,  g_rm);
    cudaGetSymbolAddress((void**)&rs,  g_rs);
    cudaGetSymbolAddress((void**)&cm,  g_cm);
    cudaGetSymbolAddress((void**)&cs,  g_cs);

    cudaFuncSetAttribute(tgemm, cudaFuncAttributeMaxDynamicSharedMemorySize, TG_SMEMB);

    const long tD  = (long)ML * DM;
    const long tH  = (long)ML * NHID;
    const long tI  = (long)ML * DI;

    // 1. squeeze proj + BN + silu
    tgemm<<<tg_grid(NHID), 256, TG_SMEMB>>>(x, DM, sq_w, DM, nullptr, h, NHID, ML, NHID, DM, 0);
    bn_stats<<<NHID / 32, dim3(32, 32)>>>(h, ML, NHID, cm, cs);
    bn_apply<<<(tH + 255) / 256, 256>>>(h, nullptr, h, cm, cs, sq_bn_g, sq_bn_b, tH, NHID, 1);

    // 2. depthwise conv5 + BN + silu
    dwconv5<<<(tH + 255) / 256, 256>>>(h, dw_w, h2);
    bn_stats<<<NHID / 32, dim3(32, 32)>>>(h2, ML, NHID, cm, cs);
    bn_apply<<<(tH + 255) / 256, 256>>>(h2, nullptr, h2, cm, cs, dw_bn_g, dw_bn_b, tH, NHID, 1);

    // 3. expand proj + BN, residual add -> x1
    tgemm<<<tg_grid(DM), 256, TG_SMEMB>>>(h2, NHID, ex_w, NHID, nullptr, mo, DM, ML, DM, NHID, 0);
    bn_stats<<<DM / 32, dim3(32, 32)>>>(mo, ML, DM, cm, cs);
    bn_apply<<<(tD + 255) / 256, 256>>>(mo, x, x1, cm, cs, ex_bn_g, ex_bn_b, tD, DM, 0);

    // 4/5. fused LN(x1) -> xn (+stats); feat_attr from stats
    ln_fuse<<<ML, 256>>>(x1, mnorm_g, mnorm_b, xn, rm, rs);
    feat_attr_k<<<dim3(DM / 256, BSZ), 256>>>(x1, rm, rs, attr_g, attr_b, out);

    // 6. in_proj -> xz (xm | z)
    tgemm<<<tg_grid(2 * DI), 256, TG_SMEMB>>>(xn, DM, in_proj_w, DM, nullptr, xz, 2 * DI, ML, 2 * DI, DM, 0);

    // 7. causal conv4 + bias + silu -> xmc
    cconv4<<<(tI + 255) / 256, 256>>>(xz, conv_w, conv_b, xmc);

    // 8. xproj -> dbc (dt | B | C)
    tgemm<<<tg_grid(DTR + 2 * DS), 256, TG_SMEMB>>>(xmc, DI, xproj_w, DI, nullptr, dbc, DTR + 2 * DS, ML, DTR + 2 * DS, DI, 0);

    // 9. dtproj + bias + softplus -> delta
    tgemm<<<tg_grid(DI), 256, TG_SMEMB>>>(dbc, DTR + 2 * DS, dtproj_w, DTR, dtproj_b, del, DI, ML, DI, DTR, 2);

    // 10/11. selective scan (+ *silu(z)) -> y
    scan_k<<<dim3(DI / 128, BSZ), 128>>>(xmc, del, dbc, xz, A_log, D_param, y);

    // 12. out_proj -> mamba_out
    tgemm<<<tg_grid(DM), 256, TG_SMEMB>>>(y, DI, out_proj_w, DI, nullptr, mo, DM, ML, DM, DI, 0);

    // 13. gate = sigmoid(xn @ gate_w^T + gate_b)
    tgemm<<<tg_grid(DM), 256, TG_SMEMB>>>(xn, DM, gate_w, DM, gate_b, gt, DM, ML, DM, DM, 3);

    // 14/15. fused x_final + LN stats; feat_id
    xfinal_ln<<<ML, 256>>>(x1, mo, gt, x, xf, rm, rs);
    feat_id_k<<<dim3(DM / 256, BSZ), 256>>>(xf, rm, rs, idn_g, idn_b, out + (long)BSZ * DM);

    // 16. BN over batch -> feat_id_bn
    idbn_k<<<DM / 256, 256>>>(out + (long)BSZ * DM, idbn_g, idbn_b, out + 2L * BSZ * DM);
}